// round 12
// baseline (speedup 1.0000x reference)
#include <cuda_runtime.h>
#include <math.h>
#include <stdint.h>

#define BB 4
#define CC 256
#define NN 8192
#define RSM 128
#define RG 16
#define RR 2048       // RSM*RG
#define NTILES 64     // NN/128
#define TFMASK 0xFFFFE000u

// ---------------- scratch (static device globals; no allocation) ----------------
__device__ float g_qk [(size_t)BB*NN*128];     // [b][n][0:64 q,64:128 k]
__device__ float g_v  [(size_t)BB*NN*256];     // [b][n][c]
__device__ float g_xt [(size_t)BB*NN*CC];      // x transposed: [b][n][c]
__device__ float g_wpt[(size_t)CC*CC];         // Wp transposed: [c][o]
__device__ float g_qp [(size_t)BB*NN*RSM];
__device__ float g_kp [(size_t)BB*NN*RSM];
__device__ float g_phi[(size_t)BB*NN*RG];
__device__ float g_kv [(size_t)BB*RR*CC];
__device__ float g_kvpart[(size_t)BB*2*RR*CC]; // split-K partials
__device__ float g_ksum[(size_t)BB*RR];
__device__ float g_kspart[(size_t)BB*2*RR];
__device__ float g_fsa[(size_t)BB*NN*CC];
__device__ float g_h  [(size_t)BB*CC*NN];
__device__ float g_psum  [(size_t)BB*NTILES*CC];
__device__ float g_psumsq[(size_t)BB*NTILES*CC];
__device__ float g_scale[CC];
__device__ float g_bias [CC];

// ================= tf32 warp-MMA helpers =========================================
// Operands stored as RAW fp32 bits; HMMA tf32 truncates low 13 mantissa bits.
__device__ __forceinline__ void mma_tf32(float* c,
    uint32_t a0, uint32_t a1, uint32_t a2, uint32_t a3, uint32_t b0, uint32_t b1){
    asm volatile(
      "mma.sync.aligned.m16n8k8.row.col.f32.tf32.tf32.f32 "
      "{%0,%1,%2,%3},{%4,%5,%6,%7},{%8,%9},{%0,%1,%2,%3};"
      : "+f"(c[0]),"+f"(c[1]),"+f"(c[2]),"+f"(c[3])
      : "r"(a0),"r"(a1),"r"(a2),"r"(a3),"r"(b0),"r"(b1));
}

__device__ __forceinline__ uint32_t smem_u32(const void* p){
    uint32_t a; asm("{ .reg .u64 t; cvta.to.shared.u64 t, %1; cvt.u32.u64 %0, t; }":"=r"(a):"l"(p));
    return a;
}
__device__ __forceinline__ void cp16(uint32_t dst, const void* src){
    asm volatile("cp.async.cg.shared.global [%0], [%1], 16;"::"r"(dst),"l"(src):"memory");
}
#define CP_COMMIT() asm volatile("cp.async.commit_group;":::"memory")
#define CP_WAIT0()  asm volatile("cp.async.wait_group 0;":::"memory")

__device__ __forceinline__ float fexp(float x){
    float y; asm("ex2.approx.f32 %0, %1;" : "=f"(y) : "f"(x*1.4426950408889634f));
    return y;
}

// MMA inner phase, fragment-major A: Af index = ((half*4+mf)*4+ksidx)*128 + lane*4 + slot
// slot0=(m,k) slot1=(m+8,k) slot2=(m,k+4) slot3=(m+8,k+4); chunk = 128m x 32k = 4096 words
__device__ __forceinline__ void mma_chunk_fa(const uint32_t* Af, const uint32_t (*Bs)[264],
                                             float acc[4][4][4], int half, int c_base, int lane){
    #pragma unroll
    for(int ksidx=0;ksidx<4;ksidx++){
        const int kk=ksidx*8+(lane&3);
        uint32_t af[4][4], bf[4][2];
        #pragma unroll
        for(int mf=0;mf<4;mf++){
            uint4 v=*(const uint4*)(Af + (((half*4+mf)*4+ksidx)*128 + lane*4));
            af[mf][0]=v.x; af[mf][1]=v.y; af[mf][2]=v.z; af[mf][3]=v.w;
        }
        #pragma unroll
        for(int nf=0;nf<4;nf++){
            int c0=c_base+nf*8+(lane>>2);
            bf[nf][0]=Bs[kk][c0];
            bf[nf][1]=Bs[kk+4][c0];
        }
        #pragma unroll
        for(int mf=0;mf<4;mf++)
            #pragma unroll
            for(int nf=0;nf<4;nf++)
                mma_tf32(acc[mf][nf],af[mf][0],af[mf][1],af[mf][2],af[mf][3],bf[nf][0],bf[nf][1]);
    }
}

// MMA inner phase, warp tile 64x32, both operands pitch 136
__device__ __forceinline__ void mma_chunk(const uint32_t (*As)[136], const uint32_t (*Bs)[136],
                                          float acc[4][4][4], int m_base, int c_base, int lane){
    #pragma unroll
    for(int ks=0;ks<32;ks+=8){
        uint32_t af[4][4], bf[4][2];
        const int kk=ks+(lane&3);
        #pragma unroll
        for(int mf=0;mf<4;mf++){
            int m0=m_base+mf*16+(lane>>2);
            af[mf][0]=As[kk][m0];
            af[mf][1]=As[kk][m0+8];
            af[mf][2]=As[kk+4][m0];
            af[mf][3]=As[kk+4][m0+8];
        }
        #pragma unroll
        for(int nf=0;nf<4;nf++){
            int c0=c_base+nf*8+(lane>>2);
            bf[nf][0]=Bs[kk][c0];
            bf[nf][1]=Bs[kk+4][c0];
        }
        #pragma unroll
        for(int mf=0;mf<4;mf++)
            #pragma unroll
            for(int nf=0;nf<4;nf++)
                mma_tf32(acc[mf][nf],af[mf][0],af[mf][1],af[mf][2],af[mf][3],bf[nf][0],bf[nf][1]);
    }
}

// ---------------- kernel: QK = X^T @ [Wq;Wk]^T (scaled), tf32 hi/lo 3-pass -------
#define QK_SMEM (4*32*136*4)   // 69632 bytes: Ah, Al, Bh, Bl
__global__ __launch_bounds__(256) void qk_tf32(const float* __restrict__ x,
    const float* __restrict__ Wq, const float* __restrict__ Wk)
{
    extern __shared__ uint32_t smq[];
    uint32_t (*Ah)[136]=(uint32_t(*)[136])smq;
    uint32_t (*Al)[136]=Ah+32;
    uint32_t (*Bh)[136]=Ah+64;
    uint32_t (*Bl)[136]=Ah+96;
    const int nt=blockIdx.x, b=blockIdx.y;
    const int n0=nt*128;
    const int tid=threadIdx.x, lane=tid&31, wid=tid>>5;
    const int m_base=(wid>>2)*64, c_base=(wid&3)*32;

    float4 rA[4], rW[4];
    #pragma unroll
    for(int l=0;l<4;l++){
        int f4=tid+l*256;
        int kk=f4>>5, n4=(f4&31)<<2;
        rA[l]=*(const float4*)(x + ((size_t)b*CC + kk)*NN + n0+n4);
        int oo=f4>>3, kc4=(f4&7)<<2;
        const float* wr=(oo<64)? (Wq+(size_t)oo*CC) : (Wk+(size_t)(oo-64)*CC);
        rW[l]=*(const float4*)(wr + kc4);
    }
    float acc[4][4][4];
    #pragma unroll
    for(int a=0;a<4;a++)
        #pragma unroll
        for(int bq=0;bq<4;bq++)
            #pragma unroll
            for(int cq=0;cq<4;cq++) acc[a][bq][cq]=0.0f;

    for(int it=0; it<8; ++it){
        __syncthreads();
        #pragma unroll
        for(int l=0;l<4;l++){
            int f4=tid+l*256;
            int kk=f4>>5, n4=(f4&31)<<2;
            uint4 hv;
            hv.x=__float_as_uint(rA[l].x)&TFMASK; hv.y=__float_as_uint(rA[l].y)&TFMASK;
            hv.z=__float_as_uint(rA[l].z)&TFMASK; hv.w=__float_as_uint(rA[l].w)&TFMASK;
            uint4 lv;
            lv.x=__float_as_uint(rA[l].x-__uint_as_float(hv.x));
            lv.y=__float_as_uint(rA[l].y-__uint_as_float(hv.y));
            lv.z=__float_as_uint(rA[l].z-__uint_as_float(hv.z));
            lv.w=__float_as_uint(rA[l].w-__uint_as_float(hv.w));
            *(uint4*)&Ah[kk][n4]=hv;
            *(uint4*)&Al[kk][n4]=lv;
            int oo=f4>>3, kc=(f4&7)<<2;
            float w[4]={rW[l].x,rW[l].y,rW[l].z,rW[l].w};
            #pragma unroll
            for(int e=0;e<4;e++){
                uint32_t h=__float_as_uint(w[e])&TFMASK;
                Bh[kc+e][oo]=h;
                Bl[kc+e][oo]=__float_as_uint(w[e]-__uint_as_float(h));
            }
        }
        __syncthreads();
        if(it+1<8){
            int c0=(it+1)*32;
            #pragma unroll
            for(int l=0;l<4;l++){
                int f4=tid+l*256;
                int kk=f4>>5, n4=(f4&31)<<2;
                rA[l]=*(const float4*)(x + ((size_t)b*CC + c0+kk)*NN + n0+n4);
                int oo=f4>>3, kc4=(f4&7)<<2;
                const float* wr=(oo<64)? (Wq+(size_t)oo*CC) : (Wk+(size_t)(oo-64)*CC);
                rW[l]=*(const float4*)(wr + c0+kc4);
            }
        }
        mma_chunk(Ah,Bh,acc,m_base,c_base,lane);
        mma_chunk(Ah,Bl,acc,m_base,c_base,lane);
        mma_chunk(Al,Bh,acc,m_base,c_base,lane);
    }
    const float s = 0.3535533905932738f;   // 64^-0.25
    #pragma unroll
    for(int mf=0;mf<4;mf++){
        int n = n0 + m_base + mf*16 + (lane>>2);
        #pragma unroll
        for(int nf=0;nf<4;nf++){
            int o = c_base + nf*8 + 2*(lane&3);
            float2 v0={acc[mf][nf][0]*s,acc[mf][nf][1]*s};
            float2 v1={acc[mf][nf][2]*s,acc[mf][nf][3]*s};
            *(float2*)&g_qk[((size_t)b*NN + n)*128 + o]   = v0;
            *(float2*)&g_qk[((size_t)b*NN + n+8)*128 + o] = v1;
        }
    }
}

// ---------------- kernel: V = X^T @ Wv^T (tf32 mma, raw bits) --------------------
__global__ __launch_bounds__(256) void v_tf32(const float* __restrict__ x, const float* __restrict__ Wv)
{
    __shared__ uint32_t As[32][136];   // [k=c][n]
    __shared__ uint32_t Bs[32][136];   // [k=c][o]
    const int nt=blockIdx.x, ct=blockIdx.y, b=blockIdx.z;
    const int tid=threadIdx.x, lane=tid&31, wid=tid>>5;
    const int m_base=(wid>>2)*64, c_base=(wid&3)*32;
    const int n0=nt*128;

    float4 rA[4], rW[4];
    #pragma unroll
    for(int l=0;l<4;l++){
        int f4=tid+l*256;
        int kk=f4>>5, n4=(f4&31)<<2;
        rA[l]=*(const float4*)(x + ((size_t)b*CC + kk)*NN + n0+n4);
        int oo=f4>>3, kc4=(f4&7)<<2;
        rW[l]=*(const float4*)(Wv + (size_t)(ct*128+oo)*CC + kc4);
    }
    float acc[4][4][4];
    #pragma unroll
    for(int a=0;a<4;a++)
        #pragma unroll
        for(int bq=0;bq<4;bq++)
            #pragma unroll
            for(int cq=0;cq<4;cq++) acc[a][bq][cq]=0.0f;

    for(int it=0; it<8; ++it){
        __syncthreads();
        #pragma unroll
        for(int l=0;l<4;l++){
            int f4=tid+l*256;
            int kk=f4>>5, n4=(f4&31)<<2;
            *(float4*)&As[kk][n4]=rA[l];
            int oo=f4>>3, kc=(f4&7)<<2;
            Bs[kc+0][oo]=__float_as_uint(rW[l].x); Bs[kc+1][oo]=__float_as_uint(rW[l].y);
            Bs[kc+2][oo]=__float_as_uint(rW[l].z); Bs[kc+3][oo]=__float_as_uint(rW[l].w);
        }
        __syncthreads();
        if(it+1<8){
            int c0=(it+1)*32;
            #pragma unroll
            for(int l=0;l<4;l++){
                int f4=tid+l*256;
                int kk=f4>>5, n4=(f4&31)<<2;
                rA[l]=*(const float4*)(x + ((size_t)b*CC + c0+kk)*NN + n0+n4);
                int oo=f4>>3, kc4=(f4&7)<<2;
                rW[l]=*(const float4*)(Wv + (size_t)(ct*128+oo)*CC + c0+kc4);
            }
        }
        mma_chunk(As,Bs,acc,m_base,c_base,lane);
    }
    #pragma unroll
    for(int mf=0;mf<4;mf++){
        int m = m_base + mf*16 + (lane>>2);
        #pragma unroll
        for(int nf=0;nf<4;nf++){
            int c = ct*128 + c_base + nf*8 + 2*(lane&3);
            float2 v0={acc[mf][nf][0],acc[mf][nf][1]};
            float2 v1={acc[mf][nf][2],acc[mf][nf][3]};
            *(float2*)&g_v[((size_t)b*NN + n0+m)*256 + c]   = v0;
            *(float2*)&g_v[((size_t)b*NN + n0+m+8)*256 + c] = v1;
        }
    }
}

// ---------------- feature maps (q_p, k_p) and geo RFF (phi), fast exp ------------
__global__ __launch_bounds__(256) void feat_kernel(const float* __restrict__ pos,
    const float* __restrict__ P,  const float* __restrict__ Wg1, const float* __restrict__ bg1,
    const float* __restrict__ Wg2,const float* __restrict__ bg2, const float* __restrict__ logtau,
    const float* __restrict__ omega)
{
    __shared__ float Ps[4096];
    __shared__ float Om[256];
    __shared__ float sWg1[48], sbg1[16], sWg2[256], sbg2[16];
    int tid=threadIdx.x;
    for(int i=tid;i<4096;i+=256) Ps[i]=P[i];
    if(tid<256){ Om[tid]=omega[tid]; sWg2[tid]=Wg2[tid]; }
    if(tid<48) sWg1[tid]=Wg1[tid];
    if(tid<16){ sbg1[tid]=bg1[tid]; sbg2[tid]=bg2[tid]; }
    __syncthreads();

    int b=blockIdx.y;
    int n=blockIdx.x*256 + tid;
    size_t bn=(size_t)b*NN + n;

    float lt=logtau[0];
    float tau=log1pf(expf(lt)) + 1e-6f;
    float s2t=sqrtf(2.0f*tau);
    float p0=pos[bn*3+0], p1=pos[bn*3+1], p2=pos[bn*3+2];
    float g1[16], z[16];
    #pragma unroll
    for(int d=0;d<16;d++){
        float t=fmaf(sWg1[d*3],p0,fmaf(sWg1[d*3+1],p1,fmaf(sWg1[d*3+2],p2,sbg1[d])));
        g1[d]=fmaxf(t,0.0f);
    }
    float zn=0.0f;
    #pragma unroll
    for(int d=0;d<16;d++){
        float t=sbg2[d];
        #pragma unroll
        for(int e=0;e<16;e++) t=fmaf(sWg2[d*16+e],g1[e],t);
        z[d]=t*s2t;
        zn=fmaf(z[d],z[d],zn);
    }
    zn*=0.5f;
    #pragma unroll
    for(int r=0;r<16;r++){
        float t=0.0f;
        #pragma unroll
        for(int d=0;d<16;d++) t=fmaf(z[d],Om[d*16+r],t);
        g_phi[bn*16+r]=fexp(t-zn)*0.25f;
    }

    const float* row = g_qk + bn*128;
    const float fs = 0.08838834764831845f;
    for(int which=0;which<2;which++){
        const float* qr = row + which*64;
        float proj[64];
        #pragma unroll
        for(int m=0;m<64;m++) proj[m]=0.0f;
        for(int o=0;o<64;o++){
            float qo=qr[o];
            #pragma unroll
            for(int m=0;m<64;m++) proj[m]=fmaf(qo,Ps[o*64+m],proj[m]);
        }
        float M=0.0f;
        #pragma unroll
        for(int m=0;m<64;m++) M=fmaxf(M,fabsf(proj[m]));
        float* dst=(which==0? g_qp : g_kp) + bn*128;
        #pragma unroll
        for(int m=0;m<64;m++){
            dst[m]    = fexp(proj[m]-M)*fs + 1e-6f;
            dst[64+m] = fexp(-proj[m]-M)*fs + 1e-6f;
        }
    }
}

// ================= tf32 mma GEMM 1: kv (512 thr, split-K=2, frag-major A) ========
// Af: 2 bufs x 4096 words (32 KB), Bs: [2*32][264]
#define KV_SMEM (2*4096*4 + 2*32*264*4)   // 100352 bytes
__global__ void __launch_bounds__(512,1) kv_tf32()
{
    extern __shared__ uint32_t smu[];
    uint32_t* Af = smu;                                   // [2][4096]
    uint32_t (*Bs)[264] = (uint32_t(*)[264])(smu + 8192); // [2*32][264]
    const int mt=blockIdx.x, sk=blockIdx.y, b=blockIdx.z;
    const int tid=threadIdx.x, lane=tid&31, wid=tid>>5;
    const int half=wid>>3, m_base=(wid>>3)*64, c_base=(wid&7)*32;
    const size_t bn=(size_t)b*NN;
    const int i0=mt*8;
    const int nstart = sk*4096;
    const int skk=tid>>4, si=tid&15;                   // A staging: n=skk, m=si*8..+7
    const uint32_t bB = smem_u32(&Bs[0][0]);

    // frag-major A staging base (k=skk fixed, m=si*8+j): idx = base*128 + 16j + 4*(skk&3) + slot
    const int half_s=si>>3, mf_s=(si>>1)&3, ksidx_s=skk>>3;
    const uint32_t aidx0 = (uint32_t)(((half_s*4+mf_s)*4+ksidx_s)*128
                          + (skk&3)*4 + ((si&1)|(((skk>>2)&1)<<1)));

    int browL[4], bc4L[4];
    #pragma unroll
    for(int l=0;l<4;l++){ int f4=tid+l*512; browL[l]=f4>>6; bc4L[l]=(f4&63)<<2; }

    #pragma unroll
    for(int l=0;l<4;l++)
        cp16(bB + (uint32_t)((browL[l]*264 + bc4L[l])<<2),
             g_v + (bn+nstart+browL[l])*256 + bc4L[l]);
    CP_COMMIT();
    float rphi[8]; float rkp;
    {
        const float* ph=g_phi + (bn+nstart+skk)*16 + (si&1)*8;
        *(float4*)(rphi)  =*(const float4*)(ph);
        *(float4*)(rphi+4)=*(const float4*)(ph+4);
        rkp = g_kp[(bn+nstart+skk)*128 + i0 + (si>>1)];
    }
    float acc[4][4][4];
    #pragma unroll
    for(int a=0;a<4;a++)
        #pragma unroll
        for(int bq=0;bq<4;bq++)
            #pragma unroll
            for(int cq=0;cq<4;cq++) acc[a][bq][cq]=0.0f;
    float ksA[8];
    #pragma unroll
    for(int j=0;j<8;j++) ksA[j]=0.0f;

    for(int it=0; it<128; ++it){
        const uint32_t abuf=(uint32_t)(it&1)*4096;
        float p[8];
        #pragma unroll
        for(int j=0;j<8;j++){ p[j]=rkp*rphi[j]; ksA[j]+=p[j]; }
        #pragma unroll
        for(int j=0;j<8;j++)
            Af[abuf + aidx0 + (uint32_t)j*16] = __float_as_uint(p[j]);
        CP_WAIT0();
        __syncthreads();
        if(it+1<128){
            const int n0=nstart+(it+1)*32;
            const uint32_t dst0 = bB + (uint32_t)(((it+1)&1)*32*264*4);
            #pragma unroll
            for(int l=0;l<4;l++)
                cp16(dst0 + (uint32_t)((browL[l]*264 + bc4L[l])<<2),
                     g_v + (bn+n0+browL[l])*256 + bc4L[l]);
            CP_COMMIT();
            const float* ph=g_phi + (bn+n0+skk)*16 + (si&1)*8;
            *(float4*)(rphi)  =*(const float4*)(ph);
            *(float4*)(rphi+4)=*(const float4*)(ph+4);
            rkp = g_kp[(bn+n0+skk)*128 + i0 + (si>>1)];
        }
        mma_chunk_fa(Af+abuf, Bs+(it&1)*32, acc, half, c_base, lane);
    }
    float* dst = g_kvpart + ((size_t)b*2+sk)*RR*CC;
    #pragma unroll
    for(int mf=0;mf<4;mf++){
        int m = mt*128 + m_base + mf*16 + (lane>>2);
        #pragma unroll
        for(int nf=0;nf<4;nf++){
            int c = c_base + nf*8 + 2*(lane&3);
            float2 v0={acc[mf][nf][0],acc[mf][nf][1]};
            float2 v1={acc[mf][nf][2],acc[mf][nf][3]};
            *(float2*)&dst[(size_t)m*CC + c]     = v0;
            *(float2*)&dst[(size_t)(m+8)*CC + c] = v1;
        }
    }
    __syncthreads();
    float* ksred = (float*)smu;       // 32 x 128 floats = 16 KB (fits Af region)
    *(float4*)&ksred[skk*128 + si*8]   = *(float4*)(ksA);
    *(float4*)&ksred[skk*128 + si*8+4] = *(float4*)(ksA+4);
    __syncthreads();
    if(tid<128){
        float s=0.0f;
        #pragma unroll
        for(int k=0;k<32;k++) s+=ksred[k*128+tid];
        g_kspart[((size_t)b*2+sk)*RR + mt*128 + tid]=s;
    }
}

// ---------------- util: kv reduce + ksum reduce + xt + wpt (merged) --------------
__global__ __launch_bounds__(256) void util_kernel(const float* __restrict__ x, const float* __restrict__ Wp)
{
    __shared__ float t[32][33];
    const int bx=blockIdx.x, tid=threadIdx.x;
    if(bx < 2048){
        size_t i4=(size_t)bx*256 + tid;
        size_t f=i4*4;
        size_t b=f/((size_t)RR*CC), off=f%((size_t)RR*CC);
        float4 a=*(const float4*)(g_kvpart + (b*2+0)*(size_t)RR*CC + off);
        float4 c=*(const float4*)(g_kvpart + (b*2+1)*(size_t)RR*CC + off);
        float4 o={a.x+c.x,a.y+c.y,a.z+c.z,a.w+c.w};
        *(float4*)(g_kv + b*(size_t)RR*CC + off)=o;
    } else if(bx < 2080){
        int idx=(bx-2048)*256 + tid;
        int b=idx>>11, r=idx&2047;
        g_ksum[(size_t)b*RR + r] = g_kspart[((size_t)b*2+0)*RR + r]
                                 + g_kspart[((size_t)b*2+1)*RR + r];
    } else if(bx < 10272){
        int xb = bx-2080;
        int n0=(xb&255)*32, c0=((xb>>8)&7)*32, b=xb>>11;
        int cl=tid>>5, nl=tid&31;
        #pragma unroll
        for(int i=0;i<4;i++)
            t[cl+i*8][nl] = x[((size_t)b*CC + c0+cl+i*8)*NN + n0+nl];
        __syncthreads();
        int nr=tid>>5, cc=tid&31;
        #pragma unroll
        for(int i=0;i<4;i++)
            g_xt[((size_t)b*NN + n0+nr+i*8)*CC + c0+cc] = t[cc][nr+i*8];
    } else {
        int wb = bx-10272;
        int o0=(wb&7)*32, c0=(wb>>3)*32;
        int ol=tid>>5, cl=tid&31;
        #pragma unroll
        for(int i=0;i<4;i++)
            t[ol+i*8][cl] = Wp[(size_t)(o0+ol+i*8)*CC + c0+cl];
        __syncthreads();
        int cr=tid>>5, oc=tid&31;
        #pragma unroll
        for(int i=0;i<4;i++)
            g_wpt[(size_t)(c0+cr+i*8)*CC + o0+oc] = t[oc][cr+i*8];
    }
}

// ================= tf32 mma GEMM 2: fsa (512 thr, frag-major A) + fused denom ====
#define FSA_SMEM (2*4096*4 + 2*32*264*4 + 2048*4 + 128*4)   // 109056 bytes
__global__ void __launch_bounds__(512,1) fsa_tf32()
{
    extern __shared__ uint32_t smu[];
    uint32_t* Af = smu;                                    // [2][4096]
    uint32_t (*Bs)[264] = (uint32_t(*)[264])(smu + 8192);
    float* sks    = (float*)(smu + 8192 + 2*32*264);       // 2048 floats
    float* sdenom = sks + 2048;                             // 128 floats
    const int mt=blockIdx.x, b=blockIdx.z;
    const int tid=threadIdx.x, lane=tid&31, wid=tid>>5;
    const int half=wid>>3, m_base=(wid>>3)*64, c_base=(wid&7)*32;
    const size_t bn0=(size_t)b*NN + (size_t)mt*128;
    const float* kvbase = g_kv + (size_t)b*RR*CC;
    const int sm=tid>>2, sip=tid&3;     // A staging: n-row sm, k = sip+4s
    const uint32_t bB = smem_u32(&Bs[0][0]);

    // frag-major A staging (k=sip+4s, m=sm)
    const int half_s=sm>>6, mf_s=(sm>>4)&3;
    const int lane_s=4*(sm&7)+sip, slot0=(sm>>3)&1;
    const uint32_t abase = (uint32_t)((half_s*4+mf_s)*4);

    int browL[4], bc4L[4];
    #pragma unroll
    for(int l=0;l<4;l++){ int f4=tid+l*512; browL[l]=f4>>6; bc4L[l]=(f4&63)<<2; }

    float rphi[16];
    {
        const float* ph=g_phi + (bn0+sm)*16;
        #pragma unroll
        for(int q=0;q<4;q++) *(float4*)(rphi+q*4)=*(const float4*)(ph+q*4);
    }
    #pragma unroll
    for(int l=0;l<4;l++)
        cp16(bB + (uint32_t)((browL[l]*264 + bc4L[l])<<2),
             kvbase + (size_t)browL[l]*CC + bc4L[l]);
    CP_COMMIT();
    #pragma unroll
    for(int i=0;i<4;i++) sks[tid+i*512]=g_ksum[(size_t)b*RR + tid + i*512];
    float rqp0 = g_qp[(bn0+sm)*128 + 0];
    float rqp1 = g_qp[(bn0+sm)*128 + 1];

    float acc[4][4][4];
    #pragma unroll
    for(int a=0;a<4;a++)
        #pragma unroll
        for(int bq=0;bq<4;bq++)
            #pragma unroll
            for(int cq=0;cq<4;cq++) acc[a][bq][cq]=0.0f;
    float d=0.0f;

    for(int it=0; it<64; ++it){
        const uint32_t abuf=(uint32_t)(it&1)*4096;
        #pragma unroll
        for(int s=0;s<8;s++){
            float q = (s<4)? rqp0 : rqp1;
            float v = q * rphi[(sip + 4*(s&3))&15];
            uint32_t idx = (abase + (uint32_t)(s>>1))*128 + (uint32_t)lane_s*4
                         + (uint32_t)(slot0 | ((s&1)<<1));
            Af[abuf + idx] = __float_as_uint(v);
        }
        CP_WAIT0();
        __syncthreads();
        {
            float t0=0.0f, t1=0.0f;
            const float* kr = sks + it*32;
            #pragma unroll
            for(int q=0;q<4;q++){
                float4 k0=*(const float4*)(kr + q*4);
                float4 k1=*(const float4*)(kr + 16 + q*4);
                t0=fmaf(k0.x,rphi[q*4+0],fmaf(k0.y,rphi[q*4+1],fmaf(k0.z,rphi[q*4+2],fmaf(k0.w,rphi[q*4+3],t0))));
                t1=fmaf(k1.x,rphi[q*4+0],fmaf(k1.y,rphi[q*4+1],fmaf(k1.z,rphi[q*4+2],fmaf(k1.w,rphi[q*4+3],t1))));
            }
            d = fmaf(rqp0,t0,fmaf(rqp1,t1,d));
        }
        if(it+1<64){
            const int k0=(it+1)*32;
            const uint32_t dst0 = bB + (uint32_t)(((it+1)&1)*32*264*4);
            #pragma unroll
            for(int l=0;l<4;l++)
                cp16(dst0 + (uint32_t)((browL[l]*264 + bc4L[l])<<2),
                     kvbase + (size_t)(k0+browL[l])*CC + bc4L[l]);
            CP_COMMIT();
            rqp0 = g_qp[(bn0+sm)*128 + (it+1)*2];
            rqp1 = g_qp[(bn0+sm)*128 + (it+1)*2 + 1];
        }
        mma_chunk_fa(Af+abuf, Bs+(it&1)*32, acc, half, c_base, lane);
    }
    sdenom[sm] = d + 1e-6f;   // all 4 sip threads write identical value
    __syncthreads();
    #pragma unroll
    for(int mf=0;mf<4;mf++){
        int ml = m_base + mf*16 + (lane>>2);
        float inv0 = 1.0f/sdenom[ml];
        float inv1 = 1.0f/sdenom[ml+8];
        #pragma unroll
        for(int nf=0;nf<4;nf++){
            int c = c_base + nf*8 + 2*(lane&3);
            float2 v0={acc[mf][nf][0]*inv0,acc[mf][nf][1]*inv0};
            float2 v1={acc[mf][nf][2]*inv1,acc[mf][nf][3]*inv1};
            *(float2*)&g_fsa[(bn0+ml)*CC + c]   = v0;
            *(float2*)&g_fsa[(bn0+ml+8)*CC + c] = v1;
        }
    }
}

// ---------------- h = WpT^T @ (xt - fsa)^T via cp.async, + BN partials ------------
#define H_SMEM (2*32*136*4*2)   // 69632
__global__ void __launch_bounds__(256,1) h_tf32()
{
    extern __shared__ uint32_t smu[];
    uint32_t (*As)[136] = (uint32_t(*)[136])smu;
    uint32_t (*Bs)[136] = ((uint32_t(*)[136])smu) + 64;
    __shared__ float red[128][5];
    const int mt=blockIdx.x, nt=blockIdx.y, b=blockIdx.z;
    const int o0=mt*128, n0=nt*128;
    const int tid=threadIdx.x, lane=tid&31, wid=tid>>5;
    const int m_base=(wid>>2)*64, c_base=(wid&3)*32;
    const uint32_t bA = smem_u32(&As[0][0]);

    int arowL[4], ac4L[4], boL[4], bc4L[4];
    #pragma unroll
    for(int l=0;l<4;l++){
        int f4=tid+l*256;
        arowL[l]=f4>>5; ac4L[l]=(f4&31)<<2;
        boL[l]=f4>>3;   bc4L[l]=(f4&7)<<2;
    }

    #pragma unroll
    for(int l=0;l<4;l++)
        cp16(bA + (uint32_t)((arowL[l]*136 + ac4L[l])<<2),
             g_wpt + (size_t)arowL[l]*CC + o0 + ac4L[l]);
    CP_COMMIT();
    float4 rXT[4], rF[4];
    #pragma unroll
    for(int l=0;l<4;l++){
        size_t base = ((size_t)b*NN + n0 + boL[l])*CC + bc4L[l];
        rXT[l]=*(const float4*)(g_xt + base);
        rF[l] =*(const float4*)(g_fsa + base);
    }
    float acc[4][4][4];
    #pragma unroll
    for(int a=0;a<4;a++)
        #pragma unroll
        for(int bq=0;bq<4;bq++)
            #pragma unroll
            for(int cq=0;cq<4;cq++) acc[a][bq][cq]=0.0f;

    for(int it=0; it<8; ++it){
        const int buf=(it&1)*32;
        #pragma unroll
        for(int l=0;l<4;l++){
            Bs[buf+bc4L[l]+0][boL[l]]=__float_as_uint(rXT[l].x-rF[l].x);
            Bs[buf+bc4L[l]+1][boL[l]]=__float_as_uint(rXT[l].y-rF[l].y);
            Bs[buf+bc4L[l]+2][boL[l]]=__float_as_uint(rXT[l].z-rF[l].z);
            Bs[buf+bc4L[l]+3][boL[l]]=__float_as_uint(rXT[l].w-rF[l].w);
        }
        CP_WAIT0();
        __syncthreads();
        if(it+1<8){
            const int k0=(it+1)*32;
            const uint32_t dst0 = bA + (uint32_t)(((it+1)&1)*32*136*4);
            #pragma unroll
            for(int l=0;l<4;l++)
                cp16(dst0 + (uint32_t)((arowL[l]*136 + ac4L[l])<<2),
                     g_wpt + (size_t)(k0+arowL[l])*CC + o0 + ac4L[l]);
            CP_COMMIT();
            #pragma unroll
            for(int l=0;l<4;l++){
                size_t base = ((size_t)b*NN + n0 + boL[l])*CC + k0 + bc4L[l];
                rXT[l]=*(const float4*)(g_xt + base);
                rF[l] =*(const float4*)(g_fsa + base);
            }
        }
        mma_chunk(As+buf,Bs+buf,acc,m_base,c_base,lane);
    }
    #pragma unroll
    for(int mf=0;mf<4;mf++){
        int r0 = m_base + mf*16 + (lane>>2);
        #pragma unroll
        for(int nf=0;nf<4;nf++){
            int nl = c_base + nf*8 + 2*(lane&3);
            float2 v0={acc[mf][nf][0],acc[mf][nf][1]};
            float2 v1={acc[mf][nf][2],acc[mf][nf][3]};
            *(float2*)&g_h[((size_t)b*CC + o0+r0)*NN + n0+nl]   = v0;
            *(float2*)&g_h[((size_t)b*CC + o0+r0+8)*NN + n0+nl] = v1;
        }
    }
    float s[4][2], q2[4][2];
    #pragma unroll
    for(int mf=0;mf<4;mf++){
        float a0=0.f,a1=0.f,b0=0.f,b1=0.f;
        #pragma unroll
        for(int nf=0;nf<4;nf++){
            a0+=acc[mf][nf][0]+acc[mf][nf][1];
            b0+=acc[mf][nf][0]*acc[mf][nf][0]+acc[mf][nf][1]*acc[mf][nf][1];
            a1+=acc[mf][nf][2]+acc[mf][nf][3];
            b1+=acc[mf][nf][2]*acc[mf][nf][2]+acc[mf][nf][3]*acc[mf][nf][3];
        }
        s[mf][0]=a0; s[mf][1]=a1; q2[mf][0]=b0; q2[mf][1]=b1;
    }
    #pragma unroll
    for(int mf=0;mf<4;mf++)
        #pragma unroll
        for(int hh=0;hh<2;hh++){
            s[mf][hh]  += __shfl_xor_sync(0xffffffff, s[mf][hh], 1);
            s[mf][hh]  += __shfl_xor_sync(0xffffffff, s[mf][hh], 2);
            q2[mf][hh] += __shfl_xor_sync(0xffffffff, q2[mf][hh], 1);
            q2[mf][hh] += __shfl_xor_sync(0xffffffff, q2[mf][hh], 2);
        }
    __syncthreads();
    if((lane&3)==0){
        #pragma unroll
        for(int mf=0;mf<4;mf++)
            #pragma unroll
            for(int hh=0;hh<2;hh++)
                red[m_base+mf*16+(lane>>2)+hh*8][wid&3]=s[mf][hh];
    }
    __syncthreads();
    if(tid<128){
        float t=red[tid][0]+red[tid][1]+red[tid][2]+red[tid][3];
        g_psum[((size_t)b*NTILES+nt)*CC + o0 + tid]=t;
    }
    __syncthreads();
    if((lane&3)==0){
        #pragma unroll
        for(int mf=0;mf<4;mf++)
            #pragma unroll
            for(int hh=0;hh<2;hh++)
                red[m_base+mf*16+(lane>>2)+hh*8][wid&3]=q2[mf][hh];
    }
    __syncthreads();
    if(tid<128){
        float t=red[tid][0]+red[tid][1]+red[tid][2]+red[tid][3];
        g_psumsq[((size_t)b*NTILES+nt)*CC + o0 + tid]=t;
    }
}

// ---------------- BN stats -> scale/bias ------------------------------------------
__global__ void stats_kernel(const float* __restrict__ gamma, const float* __restrict__ beta)
{
    int o=threadIdx.x;
    float s=0.f,s2=0.f;
    for(int t=0;t<BB*NTILES;t++){
        s +=g_psum  [(size_t)t*CC+o];
        s2+=g_psumsq[(size_t)t*CC+o];
    }
    const float inv=1.0f/(float)((size_t)BB*NN);
    float mean=s*inv;
    float var=s2*inv - mean*mean;
    float sc=gamma[o]*rsqrtf(var+1e-5f);
    g_scale[o]=sc;
    g_bias[o]=beta[o]-mean*sc;
}

// ---------------- out = relu(BN(h)) + x --------------------------------------------
__global__ __launch_bounds__(256) void final_kernel(const float* __restrict__ x, float* __restrict__ out)
{
    size_t i4=(size_t)blockIdx.x*256 + threadIdx.x;
    size_t f=i4*4;
    int c=(int)((f/NN)%CC);
    float sc=g_scale[c], bi=g_bias[c];
    float4 h=*(const float4*)(g_h+f);
    float4 xv=*(const float4*)(x+f);
    float4 o;
    o.x=fmaxf(fmaf(h.x,sc,bi),0.0f)+xv.x;
    o.y=fmaxf(fmaf(h.y,sc,bi),0.0f)+xv.y;
    o.z=fmaxf(fmaf(h.z,sc,bi),0.0f)+xv.z;
    o.w=fmaxf(fmaf(h.w,sc,bi),0.0f)+xv.w;
    *(float4*)(out+f)=o;
}

// ---------------- launch ------------------------------------------------------------
extern "C" void kernel_launch(void* const* d_in, const int* in_sizes, int n_in,
                              void* d_out, int out_size)
{
    const float* x      =(const float*)d_in[0];
    const float* pos    =(const float*)d_in[1];
    const float* Wq     =(const float*)d_in[2];
    const float* Wk     =(const float*)d_in[3];
    const float* Wv     =(const float*)d_in[4];
    const float* proj_sm=(const float*)d_in[5];
    const float* Wg1    =(const float*)d_in[6];
    const float* bg1    =(const float*)d_in[7];
    const float* Wg2    =(const float*)d_in[8];
    const float* bg2    =(const float*)d_in[9];
    const float* log_tau=(const float*)d_in[10];
    const float* omega  =(const float*)d_in[11];
    const float* Wp     =(const float*)d_in[12];
    const float* gamma  =(const float*)d_in[13];
    const float* beta   =(const float*)d_in[14];
    float* out=(float*)d_out;

    static int smem_set = 0;
    if(!smem_set){
        cudaFuncSetAttribute(qk_tf32,  cudaFuncAttributeMaxDynamicSharedMemorySize, QK_SMEM);
        cudaFuncSetAttribute(kv_tf32,  cudaFuncAttributeMaxDynamicSharedMemorySize, KV_SMEM);
        cudaFuncSetAttribute(fsa_tf32, cudaFuncAttributeMaxDynamicSharedMemorySize, FSA_SMEM);
        cudaFuncSetAttribute(h_tf32,   cudaFuncAttributeMaxDynamicSharedMemorySize, H_SMEM);
        smem_set = 1;
    }

    v_tf32      <<<dim3(64,2,BB),256>>>(x,Wv);                                       // 0
    qk_tf32     <<<dim3(64,BB),256,QK_SMEM>>>(x,Wq,Wk);                              // 1
    feat_kernel <<<dim3(32,BB),256>>>(pos,proj_sm,Wg1,bg1,Wg2,bg2,log_tau,omega);    // 2
    kv_tf32     <<<dim3(16,2,BB),512,KV_SMEM>>>();                                   // 3 (ncu slot)
    util_kernel <<<10336,256>>>(x,Wp);                                               // 4
    fsa_tf32    <<<dim3(64,1,BB),512,FSA_SMEM>>>();                                  // 5
    h_tf32      <<<dim3(2,64,BB),256,H_SMEM>>>();                                    // 6
    stats_kernel<<<1,256>>>(gamma,beta);                                             // 7
    final_kernel<<<8192,256>>>(x,out);                                               // 8
}

// round 13
// speedup vs baseline: 1.0730x; 1.0730x over previous
#include <cuda_runtime.h>
#include <math.h>
#include <stdint.h>

#define BB 4
#define CC 256
#define NN 8192
#define RSM 128
#define RG 16
#define RR 2048       // RSM*RG
#define NTILES 64     // NN/128
#define TFMASK 0xFFFFE000u

// ---------------- scratch (static device globals; no allocation) ----------------
__device__ float g_qk [(size_t)BB*NN*128];     // [b][n][0:64 q,64:128 k]
__device__ float g_v  [(size_t)BB*NN*256];     // [b][n][c]
__device__ float g_xt [(size_t)BB*NN*CC];      // x transposed: [b][n][c]
__device__ float g_wpt[(size_t)CC*CC];         // Wp transposed: [c][o]
__device__ float g_qp [(size_t)BB*NN*RSM];
__device__ float g_kp [(size_t)BB*NN*RSM];
__device__ float g_phi[(size_t)BB*NN*RG];
__device__ float g_kv [(size_t)BB*RR*CC];
__device__ float g_kvpart[(size_t)BB*2*RR*CC]; // split-K partials
__device__ float g_ksum[(size_t)BB*RR];
__device__ float g_kspart[(size_t)BB*2*RR];
__device__ float g_fsa[(size_t)BB*NN*CC];
__device__ float g_h  [(size_t)BB*CC*NN];
__device__ float g_psum  [(size_t)BB*NTILES*CC];
__device__ float g_psumsq[(size_t)BB*NTILES*CC];
__device__ float g_scale[CC];
__device__ float g_bias [CC];

// ================= tf32 warp-MMA helpers =========================================
// Operands stored as RAW fp32 bits; HMMA tf32 truncates low 13 mantissa bits.
__device__ __forceinline__ void mma_tf32(float* c,
    uint32_t a0, uint32_t a1, uint32_t a2, uint32_t a3, uint32_t b0, uint32_t b1){
    asm volatile(
      "mma.sync.aligned.m16n8k8.row.col.f32.tf32.tf32.f32 "
      "{%0,%1,%2,%3},{%4,%5,%6,%7},{%8,%9},{%0,%1,%2,%3};"
      : "+f"(c[0]),"+f"(c[1]),"+f"(c[2]),"+f"(c[3])
      : "r"(a0),"r"(a1),"r"(a2),"r"(a3),"r"(b0),"r"(b1));
}

__device__ __forceinline__ uint32_t smem_u32(const void* p){
    uint32_t a; asm("{ .reg .u64 t; cvta.to.shared.u64 t, %1; cvt.u32.u64 %0, t; }":"=r"(a):"l"(p));
    return a;
}
__device__ __forceinline__ void cp16(uint32_t dst, const void* src){
    asm volatile("cp.async.cg.shared.global [%0], [%1], 16;"::"r"(dst),"l"(src):"memory");
}
#define CP_COMMIT() asm volatile("cp.async.commit_group;":::"memory")
#define CP_WAIT0()  asm volatile("cp.async.wait_group 0;":::"memory")

__device__ __forceinline__ float fexp(float x){
    float y; asm("ex2.approx.f32 %0, %1;" : "=f"(y) : "f"(x*1.4426950408889634f));
    return y;
}

// MMA inner phase, warp tile 64x32: As[k][m](pitch136), Bs[k][c](pitch264)
__device__ __forceinline__ void mma_chunk_w(const uint32_t (*As)[136], const uint32_t (*Bs)[264],
                                            float acc[4][4][4], int m_base, int c_base, int lane){
    #pragma unroll
    for(int ks=0;ks<32;ks+=8){
        uint32_t af[4][4], bf[4][2];
        const int kk=ks+(lane&3);
        #pragma unroll
        for(int mf=0;mf<4;mf++){
            int m0=m_base+mf*16+(lane>>2);
            af[mf][0]=As[kk][m0];
            af[mf][1]=As[kk][m0+8];
            af[mf][2]=As[kk+4][m0];
            af[mf][3]=As[kk+4][m0+8];
        }
        #pragma unroll
        for(int nf=0;nf<4;nf++){
            int c0=c_base+nf*8+(lane>>2);
            bf[nf][0]=Bs[kk][c0];
            bf[nf][1]=Bs[kk+4][c0];
        }
        #pragma unroll
        for(int mf=0;mf<4;mf++)
            #pragma unroll
            for(int nf=0;nf<4;nf++)
                mma_tf32(acc[mf][nf],af[mf][0],af[mf][1],af[mf][2],af[mf][3],bf[nf][0],bf[nf][1]);
    }
}

// MMA inner phase, warp tile 64x32, both operands pitch 136
__device__ __forceinline__ void mma_chunk(const uint32_t (*As)[136], const uint32_t (*Bs)[136],
                                          float acc[4][4][4], int m_base, int c_base, int lane){
    #pragma unroll
    for(int ks=0;ks<32;ks+=8){
        uint32_t af[4][4], bf[4][2];
        const int kk=ks+(lane&3);
        #pragma unroll
        for(int mf=0;mf<4;mf++){
            int m0=m_base+mf*16+(lane>>2);
            af[mf][0]=As[kk][m0];
            af[mf][1]=As[kk][m0+8];
            af[mf][2]=As[kk+4][m0];
            af[mf][3]=As[kk+4][m0+8];
        }
        #pragma unroll
        for(int nf=0;nf<4;nf++){
            int c0=c_base+nf*8+(lane>>2);
            bf[nf][0]=Bs[kk][c0];
            bf[nf][1]=Bs[kk+4][c0];
        }
        #pragma unroll
        for(int mf=0;mf<4;mf++)
            #pragma unroll
            for(int nf=0;nf<4;nf++)
                mma_tf32(acc[mf][nf],af[mf][0],af[mf][1],af[mf][2],af[mf][3],bf[nf][0],bf[nf][1]);
    }
}

// ---------------- kernel: QK = X^T @ [Wq;Wk]^T (scaled), tf32 hi/lo 3-pass -------
#define QK_SMEM (4*32*136*4)   // 69632 bytes: Ah, Al, Bh, Bl
__global__ __launch_bounds__(256) void qk_tf32(const float* __restrict__ x,
    const float* __restrict__ Wq, const float* __restrict__ Wk)
{
    extern __shared__ uint32_t smq[];
    uint32_t (*Ah)[136]=(uint32_t(*)[136])smq;
    uint32_t (*Al)[136]=Ah+32;
    uint32_t (*Bh)[136]=Ah+64;
    uint32_t (*Bl)[136]=Ah+96;
    const int nt=blockIdx.x, b=blockIdx.y;
    const int n0=nt*128;
    const int tid=threadIdx.x, lane=tid&31, wid=tid>>5;
    const int m_base=(wid>>2)*64, c_base=(wid&3)*32;

    float4 rA[4], rW[4];
    #pragma unroll
    for(int l=0;l<4;l++){
        int f4=tid+l*256;
        int kk=f4>>5, n4=(f4&31)<<2;
        rA[l]=*(const float4*)(x + ((size_t)b*CC + kk)*NN + n0+n4);
        int oo=f4>>3, kc4=(f4&7)<<2;
        const float* wr=(oo<64)? (Wq+(size_t)oo*CC) : (Wk+(size_t)(oo-64)*CC);
        rW[l]=*(const float4*)(wr + kc4);
    }
    float acc[4][4][4];
    #pragma unroll
    for(int a=0;a<4;a++)
        #pragma unroll
        for(int bq=0;bq<4;bq++)
            #pragma unroll
            for(int cq=0;cq<4;cq++) acc[a][bq][cq]=0.0f;

    for(int it=0; it<8; ++it){
        __syncthreads();
        #pragma unroll
        for(int l=0;l<4;l++){
            int f4=tid+l*256;
            int kk=f4>>5, n4=(f4&31)<<2;
            uint4 hv;
            hv.x=__float_as_uint(rA[l].x)&TFMASK; hv.y=__float_as_uint(rA[l].y)&TFMASK;
            hv.z=__float_as_uint(rA[l].z)&TFMASK; hv.w=__float_as_uint(rA[l].w)&TFMASK;
            uint4 lv;
            lv.x=__float_as_uint(rA[l].x-__uint_as_float(hv.x));
            lv.y=__float_as_uint(rA[l].y-__uint_as_float(hv.y));
            lv.z=__float_as_uint(rA[l].z-__uint_as_float(hv.z));
            lv.w=__float_as_uint(rA[l].w-__uint_as_float(hv.w));
            *(uint4*)&Ah[kk][n4]=hv;
            *(uint4*)&Al[kk][n4]=lv;
            int oo=f4>>3, kc=(f4&7)<<2;
            float w[4]={rW[l].x,rW[l].y,rW[l].z,rW[l].w};
            #pragma unroll
            for(int e=0;e<4;e++){
                uint32_t h=__float_as_uint(w[e])&TFMASK;
                Bh[kc+e][oo]=h;
                Bl[kc+e][oo]=__float_as_uint(w[e]-__uint_as_float(h));
            }
        }
        __syncthreads();
        if(it+1<8){
            int c0=(it+1)*32;
            #pragma unroll
            for(int l=0;l<4;l++){
                int f4=tid+l*256;
                int kk=f4>>5, n4=(f4&31)<<2;
                rA[l]=*(const float4*)(x + ((size_t)b*CC + c0+kk)*NN + n0+n4);
                int oo=f4>>3, kc4=(f4&7)<<2;
                const float* wr=(oo<64)? (Wq+(size_t)oo*CC) : (Wk+(size_t)(oo-64)*CC);
                rW[l]=*(const float4*)(wr + c0+kc4);
            }
        }
        mma_chunk(Ah,Bh,acc,m_base,c_base,lane);
        mma_chunk(Ah,Bl,acc,m_base,c_base,lane);
        mma_chunk(Al,Bh,acc,m_base,c_base,lane);
    }
    const float s = 0.3535533905932738f;   // 64^-0.25
    #pragma unroll
    for(int mf=0;mf<4;mf++){
        int n = n0 + m_base + mf*16 + (lane>>2);
        #pragma unroll
        for(int nf=0;nf<4;nf++){
            int o = c_base + nf*8 + 2*(lane&3);
            float2 v0={acc[mf][nf][0]*s,acc[mf][nf][1]*s};
            float2 v1={acc[mf][nf][2]*s,acc[mf][nf][3]*s};
            *(float2*)&g_qk[((size_t)b*NN + n)*128 + o]   = v0;
            *(float2*)&g_qk[((size_t)b*NN + n+8)*128 + o] = v1;
        }
    }
}

// ---------------- kernel: V = X^T @ Wv^T (tf32 mma, raw bits) --------------------
__global__ __launch_bounds__(256) void v_tf32(const float* __restrict__ x, const float* __restrict__ Wv)
{
    __shared__ uint32_t As[32][136];   // [k=c][n]
    __shared__ uint32_t Bs[32][136];   // [k=c][o]
    const int nt=blockIdx.x, ct=blockIdx.y, b=blockIdx.z;
    const int tid=threadIdx.x, lane=tid&31, wid=tid>>5;
    const int m_base=(wid>>2)*64, c_base=(wid&3)*32;
    const int n0=nt*128;

    float4 rA[4], rW[4];
    #pragma unroll
    for(int l=0;l<4;l++){
        int f4=tid+l*256;
        int kk=f4>>5, n4=(f4&31)<<2;
        rA[l]=*(const float4*)(x + ((size_t)b*CC + kk)*NN + n0+n4);
        int oo=f4>>3, kc4=(f4&7)<<2;
        rW[l]=*(const float4*)(Wv + (size_t)(ct*128+oo)*CC + kc4);
    }
    float acc[4][4][4];
    #pragma unroll
    for(int a=0;a<4;a++)
        #pragma unroll
        for(int bq=0;bq<4;bq++)
            #pragma unroll
            for(int cq=0;cq<4;cq++) acc[a][bq][cq]=0.0f;

    for(int it=0; it<8; ++it){
        __syncthreads();
        #pragma unroll
        for(int l=0;l<4;l++){
            int f4=tid+l*256;
            int kk=f4>>5, n4=(f4&31)<<2;
            *(float4*)&As[kk][n4]=rA[l];
            int oo=f4>>3, kc=(f4&7)<<2;
            Bs[kc+0][oo]=__float_as_uint(rW[l].x); Bs[kc+1][oo]=__float_as_uint(rW[l].y);
            Bs[kc+2][oo]=__float_as_uint(rW[l].z); Bs[kc+3][oo]=__float_as_uint(rW[l].w);
        }
        __syncthreads();
        if(it+1<8){
            int c0=(it+1)*32;
            #pragma unroll
            for(int l=0;l<4;l++){
                int f4=tid+l*256;
                int kk=f4>>5, n4=(f4&31)<<2;
                rA[l]=*(const float4*)(x + ((size_t)b*CC + c0+kk)*NN + n0+n4);
                int oo=f4>>3, kc4=(f4&7)<<2;
                rW[l]=*(const float4*)(Wv + (size_t)(ct*128+oo)*CC + c0+kc4);
            }
        }
        mma_chunk(As,Bs,acc,m_base,c_base,lane);
    }
    #pragma unroll
    for(int mf=0;mf<4;mf++){
        int m = m_base + mf*16 + (lane>>2);
        #pragma unroll
        for(int nf=0;nf<4;nf++){
            int c = ct*128 + c_base + nf*8 + 2*(lane&3);
            float2 v0={acc[mf][nf][0],acc[mf][nf][1]};
            float2 v1={acc[mf][nf][2],acc[mf][nf][3]};
            *(float2*)&g_v[((size_t)b*NN + n0+m)*256 + c]   = v0;
            *(float2*)&g_v[((size_t)b*NN + n0+m+8)*256 + c] = v1;
        }
    }
}

// ---------------- feature maps (q_p, k_p) and geo RFF (phi), fast exp ------------
__global__ __launch_bounds__(256) void feat_kernel(const float* __restrict__ pos,
    const float* __restrict__ P,  const float* __restrict__ Wg1, const float* __restrict__ bg1,
    const float* __restrict__ Wg2,const float* __restrict__ bg2, const float* __restrict__ logtau,
    const float* __restrict__ omega)
{
    __shared__ float Ps[4096];
    __shared__ float Om[256];
    __shared__ float sWg1[48], sbg1[16], sWg2[256], sbg2[16];
    int tid=threadIdx.x;
    for(int i=tid;i<4096;i+=256) Ps[i]=P[i];
    if(tid<256){ Om[tid]=omega[tid]; sWg2[tid]=Wg2[tid]; }
    if(tid<48) sWg1[tid]=Wg1[tid];
    if(tid<16){ sbg1[tid]=bg1[tid]; sbg2[tid]=bg2[tid]; }
    __syncthreads();

    int b=blockIdx.y;
    int n=blockIdx.x*256 + tid;
    size_t bn=(size_t)b*NN + n;

    float lt=logtau[0];
    float tau=log1pf(expf(lt)) + 1e-6f;
    float s2t=sqrtf(2.0f*tau);
    float p0=pos[bn*3+0], p1=pos[bn*3+1], p2=pos[bn*3+2];
    float g1[16], z[16];
    #pragma unroll
    for(int d=0;d<16;d++){
        float t=fmaf(sWg1[d*3],p0,fmaf(sWg1[d*3+1],p1,fmaf(sWg1[d*3+2],p2,sbg1[d])));
        g1[d]=fmaxf(t,0.0f);
    }
    float zn=0.0f;
    #pragma unroll
    for(int d=0;d<16;d++){
        float t=sbg2[d];
        #pragma unroll
        for(int e=0;e<16;e++) t=fmaf(sWg2[d*16+e],g1[e],t);
        z[d]=t*s2t;
        zn=fmaf(z[d],z[d],zn);
    }
    zn*=0.5f;
    #pragma unroll
    for(int r=0;r<16;r++){
        float t=0.0f;
        #pragma unroll
        for(int d=0;d<16;d++) t=fmaf(z[d],Om[d*16+r],t);
        g_phi[bn*16+r]=fexp(t-zn)*0.25f;
    }

    const float* row = g_qk + bn*128;
    const float fs = 0.08838834764831845f;
    for(int which=0;which<2;which++){
        const float* qr = row + which*64;
        float proj[64];
        #pragma unroll
        for(int m=0;m<64;m++) proj[m]=0.0f;
        for(int o=0;o<64;o++){
            float qo=qr[o];
            #pragma unroll
            for(int m=0;m<64;m++) proj[m]=fmaf(qo,Ps[o*64+m],proj[m]);
        }
        float M=0.0f;
        #pragma unroll
        for(int m=0;m<64;m++) M=fmaxf(M,fabsf(proj[m]));
        float* dst=(which==0? g_qp : g_kp) + bn*128;
        #pragma unroll
        for(int m=0;m<64;m++){
            dst[m]    = fexp(proj[m]-M)*fs + 1e-6f;
            dst[64+m] = fexp(-proj[m]-M)*fs + 1e-6f;
        }
    }
}

// ================= tf32 mma GEMM 1: kv (512 thr, split-K=2) + fused ksum =========
#define KVFSA_SMEM (2*32*136*4 + 2*32*264*4)   // 102400 bytes
__global__ void __launch_bounds__(512,1) kv_tf32()
{
    extern __shared__ uint32_t smu[];
    uint32_t (*As)[136] = (uint32_t(*)[136])smu;               // [2*32][136]
    uint32_t (*Bs)[264] = (uint32_t(*)[264])(smu + 2*32*136);  // [2*32][264]
    const int mt=blockIdx.x, sk=blockIdx.y, b=blockIdx.z;
    const int tid=threadIdx.x, lane=tid&31, wid=tid>>5;
    const int m_base=(wid>>3)*64, c_base=(wid&7)*32;   // 2 x 8 warp grid
    const size_t bn=(size_t)b*NN;
    const int i0=mt*8;
    const int nstart = sk*4096;
    const int skk=tid>>4, si=tid&15;                   // A staging: n=skk, m=si*8..+7
    const uint32_t bB = smem_u32(&Bs[0][0]);

    int browL[4], bc4L[4];
    #pragma unroll
    for(int l=0;l<4;l++){ int f4=tid+l*512; browL[l]=f4>>6; bc4L[l]=(f4&63)<<2; }

    #pragma unroll
    for(int l=0;l<4;l++)
        cp16(bB + (uint32_t)((browL[l]*264 + bc4L[l])<<2),
             g_v + (bn+nstart+browL[l])*256 + bc4L[l]);
    CP_COMMIT();
    float rphi[8]; float rkp;
    {
        const float* ph=g_phi + (bn+nstart+skk)*16 + (si&1)*8;
        *(float4*)(rphi)  =*(const float4*)(ph);
        *(float4*)(rphi+4)=*(const float4*)(ph+4);
        rkp = g_kp[(bn+nstart+skk)*128 + i0 + (si>>1)];
    }
    float acc[4][4][4];
    #pragma unroll
    for(int a=0;a<4;a++)
        #pragma unroll
        for(int bq=0;bq<4;bq++)
            #pragma unroll
            for(int cq=0;cq<4;cq++) acc[a][bq][cq]=0.0f;
    float ksA[8];
    #pragma unroll
    for(int j=0;j<8;j++) ksA[j]=0.0f;

    for(int it=0; it<128; ++it){
        const int buf=(it&1)*32;
        float p[8];
        #pragma unroll
        for(int j=0;j<8;j++){ p[j]=rkp*rphi[j]; ksA[j]+=p[j]; }
        {
            uint4 u0={__float_as_uint(p[0]),__float_as_uint(p[1]),__float_as_uint(p[2]),__float_as_uint(p[3])};
            uint4 u1={__float_as_uint(p[4]),__float_as_uint(p[5]),__float_as_uint(p[6]),__float_as_uint(p[7])};
            *(uint4*)&As[buf+skk][si*8]  =u0;
            *(uint4*)&As[buf+skk][si*8+4]=u1;
        }
        CP_WAIT0();
        __syncthreads();
        if(it+1<128){
            const int n0=nstart+(it+1)*32;
            const uint32_t dst0 = bB + (uint32_t)(((it+1)&1)*32*264*4);
            #pragma unroll
            for(int l=0;l<4;l++)
                cp16(dst0 + (uint32_t)((browL[l]*264 + bc4L[l])<<2),
                     g_v + (bn+n0+browL[l])*256 + bc4L[l]);
            CP_COMMIT();
            const float* ph=g_phi + (bn+n0+skk)*16 + (si&1)*8;
            *(float4*)(rphi)  =*(const float4*)(ph);
            *(float4*)(rphi+4)=*(const float4*)(ph+4);
            rkp = g_kp[(bn+n0+skk)*128 + i0 + (si>>1)];
        }
        mma_chunk_w(As+buf,Bs+buf,acc,m_base,c_base,lane);
    }
    float* dst = g_kvpart + ((size_t)b*2+sk)*RR*CC;
    #pragma unroll
    for(int mf=0;mf<4;mf++){
        int m = mt*128 + m_base + mf*16 + (lane>>2);
        #pragma unroll
        for(int nf=0;nf<4;nf++){
            int c = c_base + nf*8 + 2*(lane&3);
            float2 v0={acc[mf][nf][0],acc[mf][nf][1]};
            float2 v1={acc[mf][nf][2],acc[mf][nf][3]};
            *(float2*)&dst[(size_t)m*CC + c]     = v0;
            *(float2*)&dst[(size_t)(m+8)*CC + c] = v1;
        }
    }
    __syncthreads();
    float* ksred = (float*)smu;       // 32 x 128 floats
    *(float4*)&ksred[skk*128 + si*8]   = *(float4*)(ksA);
    *(float4*)&ksred[skk*128 + si*8+4] = *(float4*)(ksA+4);
    __syncthreads();
    if(tid<128){
        float s=0.0f;
        #pragma unroll
        for(int k=0;k<32;k++) s+=ksred[k*128+tid];
        g_kspart[((size_t)b*2+sk)*RR + mt*128 + tid]=s;
    }
}

// ---------------- util: kv reduce + ksum reduce + xt + wpt (merged) --------------
__global__ __launch_bounds__(256) void util_kernel(const float* __restrict__ x, const float* __restrict__ Wp)
{
    __shared__ float t[32][33];
    const int bx=blockIdx.x, tid=threadIdx.x;
    if(bx < 2048){
        size_t i4=(size_t)bx*256 + tid;
        size_t f=i4*4;
        size_t b=f/((size_t)RR*CC), off=f%((size_t)RR*CC);
        float4 a=*(const float4*)(g_kvpart + (b*2+0)*(size_t)RR*CC + off);
        float4 c=*(const float4*)(g_kvpart + (b*2+1)*(size_t)RR*CC + off);
        float4 o={a.x+c.x,a.y+c.y,a.z+c.z,a.w+c.w};
        *(float4*)(g_kv + b*(size_t)RR*CC + off)=o;
    } else if(bx < 2080){
        int idx=(bx-2048)*256 + tid;
        int b=idx>>11, r=idx&2047;
        g_ksum[(size_t)b*RR + r] = g_kspart[((size_t)b*2+0)*RR + r]
                                 + g_kspart[((size_t)b*2+1)*RR + r];
    } else if(bx < 10272){
        int xb = bx-2080;
        int n0=(xb&255)*32, c0=((xb>>8)&7)*32, b=xb>>11;
        int cl=tid>>5, nl=tid&31;
        #pragma unroll
        for(int i=0;i<4;i++)
            t[cl+i*8][nl] = x[((size_t)b*CC + c0+cl+i*8)*NN + n0+nl];
        __syncthreads();
        int nr=tid>>5, cc=tid&31;
        #pragma unroll
        for(int i=0;i<4;i++)
            g_xt[((size_t)b*NN + n0+nr+i*8)*CC + c0+cc] = t[cc][nr+i*8];
    } else {
        int wb = bx-10272;
        int o0=(wb&7)*32, c0=(wb>>3)*32;
        int ol=tid>>5, cl=tid&31;
        #pragma unroll
        for(int i=0;i<4;i++)
            t[ol+i*8][cl] = Wp[(size_t)(o0+ol+i*8)*CC + c0+cl];
        __syncthreads();
        int cr=tid>>5, oc=tid&31;
        #pragma unroll
        for(int i=0;i<4;i++)
            g_wpt[(size_t)(c0+cr+i*8)*CC + o0+oc] = t[oc][cr+i*8];
    }
}

// ================= tf32 mma GEMM 2: fsa (512 thr) + fused denom ==================
#define FSA_SMEM (KVFSA_SMEM + 2048*4 + 128*4)   // 111104 bytes
__global__ void __launch_bounds__(512,1) fsa_tf32()
{
    extern __shared__ uint32_t smu[];
    uint32_t (*As)[136] = (uint32_t(*)[136])smu;
    uint32_t (*Bs)[264] = (uint32_t(*)[264])(smu + 2*32*136);
    float* sks    = (float*)(smu + 2*32*136 + 2*32*264);   // 2048 floats
    float* sdenom = sks + 2048;                             // 128 floats
    const int mt=blockIdx.x, b=blockIdx.z;
    const int tid=threadIdx.x, lane=tid&31, wid=tid>>5;
    const int m_base=(wid>>3)*64, c_base=(wid&7)*32;
    const size_t bn0=(size_t)b*NN + (size_t)mt*128;
    const float* kvbase = g_kv + (size_t)b*RR*CC;
    const int sm=tid>>2, sip=tid&3;     // A staging: n-row sm, k = sip+4s
    const uint32_t bB = smem_u32(&Bs[0][0]);

    int browL[4], bc4L[4];
    #pragma unroll
    for(int l=0;l<4;l++){ int f4=tid+l*512; browL[l]=f4>>6; bc4L[l]=(f4&63)<<2; }

    float rphi[16];
    {
        const float* ph=g_phi + (bn0+sm)*16;
        #pragma unroll
        for(int q=0;q<4;q++) *(float4*)(rphi+q*4)=*(const float4*)(ph+q*4);
    }
    #pragma unroll
    for(int l=0;l<4;l++)
        cp16(bB + (uint32_t)((browL[l]*264 + bc4L[l])<<2),
             kvbase + (size_t)browL[l]*CC + bc4L[l]);
    CP_COMMIT();
    #pragma unroll
    for(int i=0;i<4;i++) sks[tid+i*512]=g_ksum[(size_t)b*RR + tid + i*512];
    float rqp0 = g_qp[(bn0+sm)*128 + 0];
    float rqp1 = g_qp[(bn0+sm)*128 + 1];

    float acc[4][4][4];
    #pragma unroll
    for(int a=0;a<4;a++)
        #pragma unroll
        for(int bq=0;bq<4;bq++)
            #pragma unroll
            for(int cq=0;cq<4;cq++) acc[a][bq][cq]=0.0f;
    float d=0.0f;

    for(int it=0; it<64; ++it){
        const int buf=(it&1)*32;
        #pragma unroll
        for(int s=0;s<8;s++){
            int kk = sip + 4*s;
            float q = (s<4)? rqp0 : rqp1;
            As[buf+kk][sm] = __float_as_uint(q * rphi[(sip + 4*(s&3))&15]);
        }
        CP_WAIT0();
        __syncthreads();
        {
            float t0=0.0f, t1=0.0f;
            const float* kr = sks + it*32;
            #pragma unroll
            for(int q=0;q<4;q++){
                float4 k0=*(const float4*)(kr + q*4);
                float4 k1=*(const float4*)(kr + 16 + q*4);
                t0=fmaf(k0.x,rphi[q*4+0],fmaf(k0.y,rphi[q*4+1],fmaf(k0.z,rphi[q*4+2],fmaf(k0.w,rphi[q*4+3],t0))));
                t1=fmaf(k1.x,rphi[q*4+0],fmaf(k1.y,rphi[q*4+1],fmaf(k1.z,rphi[q*4+2],fmaf(k1.w,rphi[q*4+3],t1))));
            }
            d = fmaf(rqp0,t0,fmaf(rqp1,t1,d));
        }
        if(it+1<64){
            const int k0=(it+1)*32;
            const uint32_t dst0 = bB + (uint32_t)(((it+1)&1)*32*264*4);
            #pragma unroll
            for(int l=0;l<4;l++)
                cp16(dst0 + (uint32_t)((browL[l]*264 + bc4L[l])<<2),
                     kvbase + (size_t)(k0+browL[l])*CC + bc4L[l]);
            CP_COMMIT();
            rqp0 = g_qp[(bn0+sm)*128 + (it+1)*2];
            rqp1 = g_qp[(bn0+sm)*128 + (it+1)*2 + 1];
        }
        mma_chunk_w(As+buf,Bs+buf,acc,m_base,c_base,lane);
    }
    sdenom[sm] = d + 1e-6f;   // all 4 sip threads write identical value
    __syncthreads();
    #pragma unroll
    for(int mf=0;mf<4;mf++){
        int ml = m_base + mf*16 + (lane>>2);
        float inv0 = 1.0f/sdenom[ml];
        float inv1 = 1.0f/sdenom[ml+8];
        #pragma unroll
        for(int nf=0;nf<4;nf++){
            int c = c_base + nf*8 + 2*(lane&3);
            float2 v0={acc[mf][nf][0]*inv0,acc[mf][nf][1]*inv0};
            float2 v1={acc[mf][nf][2]*inv1,acc[mf][nf][3]*inv1};
            *(float2*)&g_fsa[(bn0+ml)*CC + c]   = v0;
            *(float2*)&g_fsa[(bn0+ml+8)*CC + c] = v1;
        }
    }
}

// ---------------- h = WpT^T @ (xt - fsa)^T via cp.async, + BN partials ------------
#define H_SMEM (2*32*136*4*2)   // 69632
__global__ void __launch_bounds__(256,1) h_tf32()
{
    extern __shared__ uint32_t smu[];
    uint32_t (*As)[136] = (uint32_t(*)[136])smu;
    uint32_t (*Bs)[136] = ((uint32_t(*)[136])smu) + 64;
    __shared__ float red[128][5];
    const int mt=blockIdx.x, nt=blockIdx.y, b=blockIdx.z;
    const int o0=mt*128, n0=nt*128;
    const int tid=threadIdx.x, lane=tid&31, wid=tid>>5;
    const int m_base=(wid>>2)*64, c_base=(wid&3)*32;
    const uint32_t bA = smem_u32(&As[0][0]);

    int arowL[4], ac4L[4], boL[4], bc4L[4];
    #pragma unroll
    for(int l=0;l<4;l++){
        int f4=tid+l*256;
        arowL[l]=f4>>5; ac4L[l]=(f4&31)<<2;
        boL[l]=f4>>3;   bc4L[l]=(f4&7)<<2;
    }

    #pragma unroll
    for(int l=0;l<4;l++)
        cp16(bA + (uint32_t)((arowL[l]*136 + ac4L[l])<<2),
             g_wpt + (size_t)arowL[l]*CC + o0 + ac4L[l]);
    CP_COMMIT();
    float4 rXT[4], rF[4];
    #pragma unroll
    for(int l=0;l<4;l++){
        size_t base = ((size_t)b*NN + n0 + boL[l])*CC + bc4L[l];
        rXT[l]=*(const float4*)(g_xt + base);
        rF[l] =*(const float4*)(g_fsa + base);
    }
    float acc[4][4][4];
    #pragma unroll
    for(int a=0;a<4;a++)
        #pragma unroll
        for(int bq=0;bq<4;bq++)
            #pragma unroll
            for(int cq=0;cq<4;cq++) acc[a][bq][cq]=0.0f;

    for(int it=0; it<8; ++it){
        const int buf=(it&1)*32;
        #pragma unroll
        for(int l=0;l<4;l++){
            Bs[buf+bc4L[l]+0][boL[l]]=__float_as_uint(rXT[l].x-rF[l].x);
            Bs[buf+bc4L[l]+1][boL[l]]=__float_as_uint(rXT[l].y-rF[l].y);
            Bs[buf+bc4L[l]+2][boL[l]]=__float_as_uint(rXT[l].z-rF[l].z);
            Bs[buf+bc4L[l]+3][boL[l]]=__float_as_uint(rXT[l].w-rF[l].w);
        }
        CP_WAIT0();
        __syncthreads();
        if(it+1<8){
            const int k0=(it+1)*32;
            const uint32_t dst0 = bA + (uint32_t)(((it+1)&1)*32*136*4);
            #pragma unroll
            for(int l=0;l<4;l++)
                cp16(dst0 + (uint32_t)((arowL[l]*136 + ac4L[l])<<2),
                     g_wpt + (size_t)(k0+arowL[l])*CC + o0 + ac4L[l]);
            CP_COMMIT();
            #pragma unroll
            for(int l=0;l<4;l++){
                size_t base = ((size_t)b*NN + n0 + boL[l])*CC + k0 + bc4L[l];
                rXT[l]=*(const float4*)(g_xt + base);
                rF[l] =*(const float4*)(g_fsa + base);
            }
        }
        mma_chunk(As+buf,Bs+buf,acc,m_base,c_base,lane);
    }
    #pragma unroll
    for(int mf=0;mf<4;mf++){
        int r0 = m_base + mf*16 + (lane>>2);
        #pragma unroll
        for(int nf=0;nf<4;nf++){
            int nl = c_base + nf*8 + 2*(lane&3);
            float2 v0={acc[mf][nf][0],acc[mf][nf][1]};
            float2 v1={acc[mf][nf][2],acc[mf][nf][3]};
            *(float2*)&g_h[((size_t)b*CC + o0+r0)*NN + n0+nl]   = v0;
            *(float2*)&g_h[((size_t)b*CC + o0+r0+8)*NN + n0+nl] = v1;
        }
    }
    float s[4][2], q2[4][2];
    #pragma unroll
    for(int mf=0;mf<4;mf++){
        float a0=0.f,a1=0.f,b0=0.f,b1=0.f;
        #pragma unroll
        for(int nf=0;nf<4;nf++){
            a0+=acc[mf][nf][0]+acc[mf][nf][1];
            b0+=acc[mf][nf][0]*acc[mf][nf][0]+acc[mf][nf][1]*acc[mf][nf][1];
            a1+=acc[mf][nf][2]+acc[mf][nf][3];
            b1+=acc[mf][nf][2]*acc[mf][nf][2]+acc[mf][nf][3]*acc[mf][nf][3];
        }
        s[mf][0]=a0; s[mf][1]=a1; q2[mf][0]=b0; q2[mf][1]=b1;
    }
    #pragma unroll
    for(int mf=0;mf<4;mf++)
        #pragma unroll
        for(int hh=0;hh<2;hh++){
            s[mf][hh]  += __shfl_xor_sync(0xffffffff, s[mf][hh], 1);
            s[mf][hh]  += __shfl_xor_sync(0xffffffff, s[mf][hh], 2);
            q2[mf][hh] += __shfl_xor_sync(0xffffffff, q2[mf][hh], 1);
            q2[mf][hh] += __shfl_xor_sync(0xffffffff, q2[mf][hh], 2);
        }
    __syncthreads();
    if((lane&3)==0){
        #pragma unroll
        for(int mf=0;mf<4;mf++)
            #pragma unroll
            for(int hh=0;hh<2;hh++)
                red[m_base+mf*16+(lane>>2)+hh*8][wid&3]=s[mf][hh];
    }
    __syncthreads();
    if(tid<128){
        float t=red[tid][0]+red[tid][1]+red[tid][2]+red[tid][3];
        g_psum[((size_t)b*NTILES+nt)*CC + o0 + tid]=t;
    }
    __syncthreads();
    if((lane&3)==0){
        #pragma unroll
        for(int mf=0;mf<4;mf++)
            #pragma unroll
            for(int hh=0;hh<2;hh++)
                red[m_base+mf*16+(lane>>2)+hh*8][wid&3]=q2[mf][hh];
    }
    __syncthreads();
    if(tid<128){
        float t=red[tid][0]+red[tid][1]+red[tid][2]+red[tid][3];
        g_psumsq[((size_t)b*NTILES+nt)*CC + o0 + tid]=t;
    }
}

// ---------------- BN stats -> scale/bias (parallel, deterministic tree) ----------
__global__ __launch_bounds__(256) void stats_kernel(const float* __restrict__ gamma, const float* __restrict__ beta)
{
    __shared__ float ss[256], ss2[256];
    const int o=blockIdx.x, t=threadIdx.x;
    ss[t] =g_psum  [(size_t)t*CC+o];
    ss2[t]=g_psumsq[(size_t)t*CC+o];
    __syncthreads();
    #pragma unroll
    for(int st=128; st>0; st>>=1){
        if(t<st){ ss[t]+=ss[t+st]; ss2[t]+=ss2[t+st]; }
        __syncthreads();
    }
    if(t==0){
        const float inv=1.0f/(float)((size_t)BB*NN);
        float mean=ss[0]*inv;
        float var=ss2[0]*inv - mean*mean;
        float sc=gamma[o]*rsqrtf(var+1e-5f);
        g_scale[o]=sc;
        g_bias[o]=beta[o]-mean*sc;
    }
}

// ---------------- out = relu(BN(h)) + x --------------------------------------------
__global__ __launch_bounds__(256) void final_kernel(const float* __restrict__ x, float* __restrict__ out)
{
    size_t i4=(size_t)blockIdx.x*256 + threadIdx.x;
    size_t f=i4*4;
    int c=(int)((f/NN)%CC);
    float sc=g_scale[c], bi=g_bias[c];
    float4 h=*(const float4*)(g_h+f);
    float4 xv=*(const float4*)(x+f);
    float4 o;
    o.x=fmaxf(fmaf(h.x,sc,bi),0.0f)+xv.x;
    o.y=fmaxf(fmaf(h.y,sc,bi),0.0f)+xv.y;
    o.z=fmaxf(fmaf(h.z,sc,bi),0.0f)+xv.z;
    o.w=fmaxf(fmaf(h.w,sc,bi),0.0f)+xv.w;
    *(float4*)(out+f)=o;
}

// ---------------- launch ------------------------------------------------------------
extern "C" void kernel_launch(void* const* d_in, const int* in_sizes, int n_in,
                              void* d_out, int out_size)
{
    const float* x      =(const float*)d_in[0];
    const float* pos    =(const float*)d_in[1];
    const float* Wq     =(const float*)d_in[2];
    const float* Wk     =(const float*)d_in[3];
    const float* Wv     =(const float*)d_in[4];
    const float* proj_sm=(const float*)d_in[5];
    const float* Wg1    =(const float*)d_in[6];
    const float* bg1    =(const float*)d_in[7];
    const float* Wg2    =(const float*)d_in[8];
    const float* bg2    =(const float*)d_in[9];
    const float* log_tau=(const float*)d_in[10];
    const float* omega  =(const float*)d_in[11];
    const float* Wp     =(const float*)d_in[12];
    const float* gamma  =(const float*)d_in[13];
    const float* beta   =(const float*)d_in[14];
    float* out=(float*)d_out;

    static int smem_set = 0;
    if(!smem_set){
        cudaFuncSetAttribute(qk_tf32,  cudaFuncAttributeMaxDynamicSharedMemorySize, QK_SMEM);
        cudaFuncSetAttribute(kv_tf32,  cudaFuncAttributeMaxDynamicSharedMemorySize, KVFSA_SMEM);
        cudaFuncSetAttribute(fsa_tf32, cudaFuncAttributeMaxDynamicSharedMemorySize, FSA_SMEM);
        cudaFuncSetAttribute(h_tf32,   cudaFuncAttributeMaxDynamicSharedMemorySize, H_SMEM);
        smem_set = 1;
    }

    v_tf32      <<<dim3(64,2,BB),256>>>(x,Wv);                                       // 0
    qk_tf32     <<<dim3(64,BB),256,QK_SMEM>>>(x,Wq,Wk);                              // 1
    feat_kernel <<<dim3(32,BB),256>>>(pos,proj_sm,Wg1,bg1,Wg2,bg2,log_tau,omega);    // 2
    kv_tf32     <<<dim3(16,2,BB),512,KVFSA_SMEM>>>();                                // 3 (ncu slot)
    util_kernel <<<10336,256>>>(x,Wp);                                               // 4
    fsa_tf32    <<<dim3(64,1,BB),512,FSA_SMEM>>>();                                  // 5
    h_tf32      <<<dim3(2,64,BB),256,H_SMEM>>>();                                    // 6
    stats_kernel<<<256,256>>>(gamma,beta);                                           // 7
    final_kernel<<<8192,256>>>(x,out);                                               // 8
}